// round 2
// baseline (speedup 1.0000x reference)
#include <cuda_runtime.h>

#define N_NODES 16384
#define N_MEM   32
#define DIM     16
#define N_REL   64
#define RELPAD  260           // floats per relation row in SMEM (16B-aligned, spreads banks)
#define WPAD    17            // W row pad: 17*d mod 32 distinct for d=0..15 -> conflict-free

__global__ __launch_bounds__(256)
void ripple_kernel(const int*   __restrict__ nodes,
                   const int*   __restrict__ mh,
                   const int*   __restrict__ mr,
                   const int*   __restrict__ mt,
                   const float* __restrict__ ent,
                   const float* __restrict__ rel,
                   const float* __restrict__ W,
                   float*       __restrict__ out)
{
    extern __shared__ float sh[];                  // [N_REL*RELPAD] rel table, then W
    float* shW = sh + N_REL * RELPAD;              // [16*WPAD]

    // Stage relation table into shared (padded rows)
    for (int i = threadIdx.x; i < N_REL * 256; i += blockDim.x) {
        int row = i >> 8, col = i & 255;
        sh[row * RELPAD + col] = rel[i];
    }
    // Stage W (padded rows)
    for (int i = threadIdx.x; i < 256; i += blockDim.x) {
        int d = i >> 4, e = i & 15;
        shW[d * WPAD + e] = W[i];
    }
    __syncthreads();

    const int lane   = threadIdx.x & 31;
    const int warp   = (blockIdx.x * blockDim.x + threadIdx.x) >> 5;
    const int nwarps = (gridDim.x * blockDim.x) >> 5;
    const unsigned FULL = 0xffffffffu;

    for (int n = warp; n < N_NODES; n += nwarps) {
        // item embedding (broadcast load, replicated in every lane)
        float it[16];
        {
            const float4* p = reinterpret_cast<const float4*>(ent + (size_t)__ldg(nodes + n) * DIM);
            #pragma unroll
            for (int j = 0; j < 4; j++) {
                float4 v = __ldg(p + j);
                it[4*j+0] = v.x; it[4*j+1] = v.y; it[4*j+2] = v.z; it[4*j+3] = v.w;
            }
        }

        float res = 0.f;                 // this lane's output element (dim = lane&15)
        const int myd = lane & 15;

        #pragma unroll
        for (int hop = 0; hop < 2; hop++) {
            const int base = hop * (N_NODES * N_MEM) + n * N_MEM + lane;
            const int hid = __ldg(mh + base);
            const int rid = __ldg(mr + base);
            const int tid = __ldg(mt + base);

            // head entity
            float h[16];
            {
                const float4* p = reinterpret_cast<const float4*>(ent + (size_t)hid * DIM);
                #pragma unroll
                for (int j = 0; j < 4; j++) {
                    float4 v = __ldg(p + j);
                    h[4*j+0] = v.x; h[4*j+1] = v.y; h[4*j+2] = v.z; h[4*j+3] = v.w;
                }
            }

            // score = item . (R @ h)
            const float* rr = sh + rid * RELPAD;
            float score = 0.f;
            #pragma unroll
            for (int d = 0; d < 16; d++) {
                const float4* r4 = reinterpret_cast<const float4*>(rr + d * 16);
                float acc = 0.f;
                #pragma unroll
                for (int q = 0; q < 4; q++) {
                    float4 rv = r4[q];
                    acc = fmaf(rv.x, h[4*q+0], acc);
                    acc = fmaf(rv.y, h[4*q+1], acc);
                    acc = fmaf(rv.z, h[4*q+2], acc);
                    acc = fmaf(rv.w, h[4*q+3], acc);
                }
                score = fmaf(acc, it[d], score);
            }

            // softmax over the 32 memory slots (one per lane)
            float mx = score;
            #pragma unroll
            for (int s = 16; s; s >>= 1) mx = fmaxf(mx, __shfl_xor_sync(FULL, mx, s));
            float ev = __expf(score - mx);
            float sum = ev;
            #pragma unroll
            for (int s = 16; s; s >>= 1) sum += __shfl_xor_sync(FULL, sum, s);
            float p = ev / sum;

            // o = sum_m p_m * t_m  (butterfly-reduce; replicated in all lanes after)
            float o[16];
            {
                const float4* tp = reinterpret_cast<const float4*>(ent + (size_t)tid * DIM);
                #pragma unroll
                for (int j = 0; j < 4; j++) {
                    float4 v = __ldg(tp + j);
                    o[4*j+0] = p * v.x; o[4*j+1] = p * v.y;
                    o[4*j+2] = p * v.z; o[4*j+3] = p * v.w;
                }
            }
            #pragma unroll
            for (int s = 16; s; s >>= 1) {
                #pragma unroll
                for (int d = 0; d < 16; d++)
                    o[d] += __shfl_xor_sync(FULL, o[d], s);
            }

            if (hop == 0) {
                res = 2.f * o[myd];
                // item = (item + o) @ W.T : lane computes its own dim, then broadcast
                float nd = 0.f;
                #pragma unroll
                for (int e = 0; e < 16; e++)
                    nd = fmaf(it[e] + o[e], shW[myd * WPAD + e], nd);
                #pragma unroll
                for (int e = 0; e < 16; e++)
                    it[e] = __shfl_sync(FULL, nd, e);
            } else {
                res += o[myd];
            }
        }

        if (lane < 16) out[n * DIM + lane] = res;
    }
}

extern "C" void kernel_launch(void* const* d_in, const int* in_sizes, int n_in,
                              void* d_out, int out_size)
{
    const int*   nodes = (const int*)  d_in[0];
    const int*   mh    = (const int*)  d_in[1];
    const int*   mr    = (const int*)  d_in[2];
    const int*   mt    = (const int*)  d_in[3];
    const float* ent   = (const float*)d_in[4];
    const float* rel   = (const float*)d_in[5];
    const float* W     = (const float*)d_in[6];
    float*       out   = (float*)      d_out;

    const int smem = (N_REL * RELPAD + 16 * WPAD) * sizeof(float);   // ~67.6 KB
    cudaFuncSetAttribute(ripple_kernel, cudaFuncAttributeMaxDynamicSharedMemorySize, smem);

    const int blocks = 148 * 3;   // persistent-ish: limits relation-table replication traffic
    ripple_kernel<<<blocks, 256, smem>>>(nodes, mh, mr, mt, ent, rel, W, out);
}